// round 15
// baseline (speedup 1.0000x reference)
#include <cuda_runtime.h>

#define T_LEN   4096
#define IN_SZ   128
#define R_SZ    2048
#define NCTA    128
#define ROWS_PER_CTA 16       // 2048 / 128
#define THREADS_SCAN 256
#define SLOTS_PER_CTA 8       // 6 used chunks + 2 pad -> 128B line-aligned group
#define NREP 4                // replica count (consumer bid & 3 selects)
#define NSLOT (NCTA * SLOTS_PER_CTA)     // 1024 slots per replica
#define INV_SQRT_R 0.022097086912079608f // 1/sqrt(2048)

// Scratch: batched input projection U[t][r] = input[t] @ W_in^T + bias
__device__ float g_U[(size_t)T_LEN * R_SZ];
// Self-validating state chunks {d0,d1,d2,tag}, double-buffered by parity,
// REPLICATED 4x with each producer CTA's group padded to one 128B line.
// Aligned STG.128 is single-copy atomic: tag==t validates the 3 data floats.
__device__ __align__(128) float4 g_chunks[2][NREP][NSLOT];

__device__ __forceinline__ float4 ld_chunk_volatile(const float4* p) {
    float4 v;
    asm volatile("ld.volatile.global.v4.f32 {%0,%1,%2,%3}, [%4];"
                 : "=f"(v.x), "=f"(v.y), "=f"(v.z), "=f"(v.w)
                 : "l"(p) : "memory");
    return v;
}
__device__ __forceinline__ void st_chunk_volatile(float4* p, float4 v) {
    asm volatile("st.volatile.global.v4.f32 [%0], {%1,%2,%3,%4};"
                 :: "l"(p), "f"(v.x), "f"(v.y), "f"(v.z), "f"(v.w)
                 : "memory");
}

// ---------------------------------------------------------------------------
// Reset all chunk tags (stale tags from a previous graph replay would
// otherwise satisfy this replay's polls with stale data).
// 2 * NREP * NSLOT = 8192 float4s.
// ---------------------------------------------------------------------------
__global__ void init_kernel() {
    int i = blockIdx.x * blockDim.x + threadIdx.x;
    ((float4*)g_chunks)[i] = make_float4(0.f, 0.f, 0.f, 0.f);
}

// ---------------------------------------------------------------------------
// Projection GEMM: U = input @ W_in^T + bias.  (4096 x 2048, K=128)
// ---------------------------------------------------------------------------
#define PJ_KT 32
__global__ __launch_bounds__(256) void proj_kernel(
    const float* __restrict__ inp,   // [T_LEN][IN_SZ]
    const float* __restrict__ Win,   // [R_SZ][IN_SZ]
    const float* __restrict__ bias)  // [R_SZ]
{
    __shared__ float sA[PJ_KT][64];  // [k][t]
    __shared__ float sB[PJ_KT][64];  // [k][r]

    const int tid = threadIdx.x;
    const int t0 = blockIdx.y * 64;
    const int r0 = blockIdx.x * 64;
    const int tx = tid & 15;
    const int ty = tid >> 4;

    float acc[4][4];
#pragma unroll
    for (int i = 0; i < 4; i++)
#pragma unroll
        for (int j = 0; j < 4; j++) acc[i][j] = 0.0f;

    for (int kc = 0; kc < IN_SZ; kc += PJ_KT) {
        __syncthreads();
#pragma unroll
        for (int it = 0; it < 2; it++) {
            int i   = tid + 256 * it;
            int row = i >> 3;
            int kq  = i & 7;
            float4 va = *(const float4*)(inp + (size_t)(t0 + row) * IN_SZ + kc + 4 * kq);
            sA[4 * kq + 0][row] = va.x;
            sA[4 * kq + 1][row] = va.y;
            sA[4 * kq + 2][row] = va.z;
            sA[4 * kq + 3][row] = va.w;
            float4 vb = *(const float4*)(Win + (size_t)(r0 + row) * IN_SZ + kc + 4 * kq);
            sB[4 * kq + 0][row] = vb.x;
            sB[4 * kq + 1][row] = vb.y;
            sB[4 * kq + 2][row] = vb.z;
            sB[4 * kq + 3][row] = vb.w;
        }
        __syncthreads();
#pragma unroll
        for (int k = 0; k < PJ_KT; k++) {
            float a[4], b[4];
#pragma unroll
            for (int i = 0; i < 4; i++) a[i] = sA[k][tx + 16 * i];
#pragma unroll
            for (int j = 0; j < 4; j++) b[j] = sB[k][ty + 16 * j];
#pragma unroll
            for (int i = 0; i < 4; i++)
#pragma unroll
                for (int j = 0; j < 4; j++) acc[i][j] += a[i] * b[j];
        }
    }

#pragma unroll
    for (int j = 0; j < 4; j++) {
        const int r = r0 + ty + 16 * j;
        const float bj = bias[r];
#pragma unroll
        for (int i = 0; i < 4; i++) {
            const int t = t0 + tx + 16 * i;
            g_U[(size_t)t * R_SZ + r] = acc[i][j] + bj;
        }
    }
}

// ---------------------------------------------------------------------------
// Persistent ESN scan — R5 skeleton (6846us proven), SINGLE conceptual delta:
// replicated line-aligned chunk groups. Producer warp 7 lanes 0-23 write the
// 6 chunks x 4 replicas (one aligned 128B line per replica); consumer CTA
// polls replica (bid & 3) -> pollers per line drop ~400 -> 64.
// Consumer poll pattern is byte-identical to R5 (serial, minimal traffic).
// ---------------------------------------------------------------------------
__global__ __launch_bounds__(THREADS_SCAN, 1) void scan_kernel(
    const float* __restrict__ Wres,  // [R_SZ][R_SZ]
    float* __restrict__ out)         // [T_LEN][R_SZ]
{
    __shared__ float  s_sm[R_SZ];            // full state, 8 KB
    __shared__ float  r_sm[ROWS_PER_CTA];    // this CTA's 16 new values

    const float4* s_sm4 = (const float4*)s_sm;

    const int tid  = threadIdx.x;
    const int warp = tid >> 5;
    const int lane = tid & 31;
    const int bid  = blockIdx.x;
    const int rowA = bid * ROWS_PER_CTA + 2 * warp;

    // Preload weights: thread (warp w, lane l) owns rows {rowA,rowA+1},
    // columns 4*l + 128*k (+0..3), k = 0..15.  128 scalar f32 regs.
    float4 wA[16], wB[16];
    {
        const float* pA = Wres + (size_t)rowA * R_SZ + 4 * lane;
        const float* pB = pA + R_SZ;
#pragma unroll
        for (int k = 0; k < 16; k++) {
            wA[k] = *(const float4*)(pA + 128 * k);
            wB[k] = *(const float4*)(pB + 128 * k);
        }
    }

    // lane 0 owns rowA's carry, lane 16 owns rowA+1's carry
    const bool is_owner = (lane == 0) || (lane == 16);
    const int  my_row   = rowA + (lane >> 4);
    float xp = 0.0f;                 // previous value of my_row

    // Consumer mapping: thread tid polls producer CTA p = tid/2,
    // subs {0,1,2} (tid even) or {3,4,5} (tid odd). Rows p*16 + 3*sub.
    const int p    = tid >> 1;
    const int subB = (tid & 1) * 3;                  // 0 or 3
    const int slot0 = p * SLOTS_PER_CTA + subB;      // within replica
    const int rep   = bid & (NREP - 1);              // this CTA's replica

    for (int t = 0; t < T_LEN; t++) {
        // ---- hoisted independent load: input projection for this step ----
        float u = 0.f;
        if (is_owner) u = __ldg(g_U + (size_t)t * R_SZ + my_row);

        // ---- acquire state for step t: R5 serial polls on our replica ----
        if (t == 0) {
            for (int i = tid; i < R_SZ; i += THREADS_SCAN) s_sm[i] = 0.0f;
        } else {
            const float4* buf = g_chunks[t & 1][rep];
#pragma unroll
            for (int i = 0; i < 3; i++) {
                const int sub = subB + i;                     // 0..5
                const int row = p * ROWS_PER_CTA + 3 * sub;
                float4 v = ld_chunk_volatile(buf + slot0 + i);
                while (__float_as_int(v.w) != t)
                    v = ld_chunk_volatile(buf + slot0 + i);
                s_sm[row] = v.x;
                if (sub < 5) { s_sm[row + 1] = v.y; s_sm[row + 2] = v.z; }
            }
        }
        __syncthreads();

        // ---- register-resident matvec (R5-proven 2-accumulator form) ----
        float a0 = 0.f, a1 = 0.f;
#pragma unroll
        for (int k = 0; k < 16; k++) {
            const float4 s4 = s_sm4[lane + 32 * k];
            a0 += wA[k].x * s4.x; a0 += wA[k].y * s4.y;
            a0 += wA[k].z * s4.z; a0 += wA[k].w * s4.w;
            a1 += wB[k].x * s4.x; a1 += wB[k].y * s4.y;
            a1 += wB[k].z * s4.z; a1 += wB[k].w * s4.w;
        }

        // ---- split-half reduction: lane 0 -> row A, lane 16 -> row B ----
        a0 += __shfl_xor_sync(0xffffffffu, a0, 16);
        a1 += __shfl_xor_sync(0xffffffffu, a1, 16);
        float v = (lane < 16) ? a0 : a1;
#pragma unroll
        for (int off = 8; off > 0; off >>= 1)
            v += __shfl_xor_sync(0xffffffffu, v, off);

        if (is_owner) {
            const float x = 0.1f * xp + 0.9f * erff(v + u) * INV_SQRT_R;
            xp = x;
            r_sm[2 * warp + (lane >> 4)] = x;
        }
        __syncthreads();

        // ---- publish: warp 7 lanes 0-23 write 6 chunks x 4 replicas,
        //      one STG.128 per lane, each replica one aligned 128B line.
        //      Plain output store by warp 6. ----
        if (warp == 7 && lane < 6 * NREP) {
            const int r   = lane / 6;         // replica
            const int sub = lane % 6;         // chunk within group
            const int r3  = 3 * sub;
            float4 c;
            c.x = r_sm[r3];
            c.y = (sub < 5) ? r_sm[r3 + 1] : 0.0f;
            c.z = (sub < 5) ? r_sm[r3 + 2] : 0.0f;
            c.w = __int_as_float(t + 1);
            st_chunk_volatile(&g_chunks[(t + 1) & 1][r][bid * SLOTS_PER_CTA + sub], c);
        }
        if (warp == 6 && lane < 4) {
            float4* dst = (float4*)(out + (size_t)t * R_SZ + bid * ROWS_PER_CTA);
            dst[lane] = ((const float4*)r_sm)[lane];
        }
    }
}

// ---------------------------------------------------------------------------
extern "C" void kernel_launch(void* const* d_in, const int* in_sizes, int n_in,
                              void* d_out, int out_size)
{
    const float* input = (const float*)d_in[0];  // [4096][128]
    const float* Win   = (const float*)d_in[1];  // [2048][128]
    const float* Wres  = (const float*)d_in[2];  // [2048][2048]
    const float* bias  = (const float*)d_in[3];  // [2048]
    float* out = (float*)d_out;                  // [4096][2048]

    init_kernel<<<(2 * NREP * NSLOT) / 256, 256>>>();

    dim3 pg(R_SZ / 64, T_LEN / 64);              // (32, 64)
    proj_kernel<<<pg, 256>>>(input, Win, bias);

    scan_kernel<<<NCTA, THREADS_SCAN>>>(Wres, out);
}

// round 16
// speedup vs baseline: 1.0285x; 1.0285x over previous
#include <cuda_runtime.h>

#define T_LEN   4096
#define IN_SZ   128
#define R_SZ    2048
#define NCTA    128
#define ROWS_PER_CTA 16       // 2048 / 128
#define THREADS_SCAN 256
#define CHUNKS_PER_CTA 6      // 16 rows -> 5 chunks x3 + 1 chunk x1
#define NCHUNK (NCTA * CHUNKS_PER_CTA)   // 768 == THREADS_SCAN * 3
#define INV_SQRT_R 0.022097086912079608f // 1/sqrt(2048)

// Scratch: batched input projection U[t][r] = input[t] @ W_in^T + bias
__device__ float g_U[(size_t)T_LEN * R_SZ];
// Self-validating state chunks: {d0,d1,d2, tag_as_float}, double-buffered by
// step parity. A 16B aligned STG.128 is single-copy atomic, so tag==t implies
// the 3 data floats in the same word are from step t. No fences, no flags.
__device__ float4 g_chunks[2][NCHUNK];

__device__ __forceinline__ float4 ld_chunk_volatile(const float4* p) {
    float4 v;
    asm volatile("ld.volatile.global.v4.f32 {%0,%1,%2,%3}, [%4];"
                 : "=f"(v.x), "=f"(v.y), "=f"(v.z), "=f"(v.w)
                 : "l"(p) : "memory");
    return v;
}
__device__ __forceinline__ void st_chunk_volatile(float4* p, float4 v) {
    asm volatile("st.volatile.global.v4.f32 [%0], {%1,%2,%3,%4};"
                 :: "l"(p), "f"(v.x), "f"(v.y), "f"(v.z), "f"(v.w)
                 : "memory");
}
// packed 2xf32 FMA (PTX ISA 8.6, sm_100+): d += a*b elementwise on f32 pairs
__device__ __forceinline__ void fma2(unsigned long long& d,
                                     unsigned long long a,
                                     unsigned long long b) {
    asm("fma.rn.f32x2 %0, %1, %2, %0;" : "+l"(d) : "l"(a), "l"(b));
}
__device__ __forceinline__ float unpack_sum(unsigned long long v) {
    float lo = __uint_as_float((unsigned)(v & 0xffffffffULL));
    float hi = __uint_as_float((unsigned)(v >> 32));
    return lo + hi;
}

// ---------------------------------------------------------------------------
// Reset all chunk tags (stale tags from a previous graph replay would
// otherwise satisfy this replay's polls with stale data).
// ---------------------------------------------------------------------------
__global__ void init_kernel() {
    int i = blockIdx.x * blockDim.x + threadIdx.x;   // 0 .. 2*NCHUNK-1
    ((float4*)g_chunks)[i] = make_float4(0.f, 0.f, 0.f, 0.f);
}

// ---------------------------------------------------------------------------
// Projection GEMM: U = input @ W_in^T + bias.  (4096 x 2048, K=128)
// ---------------------------------------------------------------------------
#define PJ_KT 32
__global__ __launch_bounds__(256) void proj_kernel(
    const float* __restrict__ inp,   // [T_LEN][IN_SZ]
    const float* __restrict__ Win,   // [R_SZ][IN_SZ]
    const float* __restrict__ bias)  // [R_SZ]
{
    __shared__ float sA[PJ_KT][64];  // [k][t]
    __shared__ float sB[PJ_KT][64];  // [k][r]

    const int tid = threadIdx.x;
    const int t0 = blockIdx.y * 64;
    const int r0 = blockIdx.x * 64;
    const int tx = tid & 15;
    const int ty = tid >> 4;

    float acc[4][4];
#pragma unroll
    for (int i = 0; i < 4; i++)
#pragma unroll
        for (int j = 0; j < 4; j++) acc[i][j] = 0.0f;

    for (int kc = 0; kc < IN_SZ; kc += PJ_KT) {
        __syncthreads();
#pragma unroll
        for (int it = 0; it < 2; it++) {
            int i   = tid + 256 * it;
            int row = i >> 3;
            int kq  = i & 7;
            float4 va = *(const float4*)(inp + (size_t)(t0 + row) * IN_SZ + kc + 4 * kq);
            sA[4 * kq + 0][row] = va.x;
            sA[4 * kq + 1][row] = va.y;
            sA[4 * kq + 2][row] = va.z;
            sA[4 * kq + 3][row] = va.w;
            float4 vb = *(const float4*)(Win + (size_t)(r0 + row) * IN_SZ + kc + 4 * kq);
            sB[4 * kq + 0][row] = vb.x;
            sB[4 * kq + 1][row] = vb.y;
            sB[4 * kq + 2][row] = vb.z;
            sB[4 * kq + 3][row] = vb.w;
        }
        __syncthreads();
#pragma unroll
        for (int k = 0; k < PJ_KT; k++) {
            float a[4], b[4];
#pragma unroll
            for (int i = 0; i < 4; i++) a[i] = sA[k][tx + 16 * i];
#pragma unroll
            for (int j = 0; j < 4; j++) b[j] = sB[k][ty + 16 * j];
#pragma unroll
            for (int i = 0; i < 4; i++)
#pragma unroll
                for (int j = 0; j < 4; j++) acc[i][j] += a[i] * b[j];
        }
    }

#pragma unroll
    for (int j = 0; j < 4; j++) {
        const int r = r0 + ty + 16 * j;
        const float bj = bias[r];
#pragma unroll
        for (int i = 0; i < 4; i++) {
            const int t = t0 + tx + 16 * i;
            g_U[(size_t)t * R_SZ + r] = acc[i][j] + bj;
        }
    }
}

// ---------------------------------------------------------------------------
// Persistent ESN scan — R5 skeleton (6846us proven), SINGLE delta:
// the inner product uses fma.rn.f32x2 (packed 2xf32) on the same float4
// weight registers (reinterpreted as aligned b64 pairs) -> FFMA issue per
// SMSP halves, 512 -> 256 cyc/step. All sync/poll/publish code is R5-exact.
// ---------------------------------------------------------------------------
__global__ __launch_bounds__(THREADS_SCAN, 1) void scan_kernel(
    const float* __restrict__ Wres,  // [R_SZ][R_SZ]
    float* __restrict__ out)         // [T_LEN][R_SZ]
{
    __shared__ float  s_sm[R_SZ];            // full state, 8 KB
    __shared__ float  r_sm[ROWS_PER_CTA];    // this CTA's 16 new values

    const float4* s_sm4 = (const float4*)s_sm;

    const int tid  = threadIdx.x;
    const int warp = tid >> 5;
    const int lane = tid & 31;
    const int bid  = blockIdx.x;
    const int rowA = bid * ROWS_PER_CTA + 2 * warp;

    // Preload weights: thread (warp w, lane l) owns rows {rowA,rowA+1},
    // columns 4*l + 128*k (+0..3), k = 0..15.  128 f32 regs as 32 float4
    // (each float4 = 4 consecutive aligned regs = 2 even-aligned b64 pairs).
    float4 wA[16], wB[16];
    {
        const float* pA = Wres + (size_t)rowA * R_SZ + 4 * lane;
        const float* pB = pA + R_SZ;
#pragma unroll
        for (int k = 0; k < 16; k++) {
            wA[k] = *(const float4*)(pA + 128 * k);
            wB[k] = *(const float4*)(pB + 128 * k);
        }
    }

    // lane 0 owns rowA's carry, lane 16 owns rowA+1's carry
    const bool is_owner = (lane == 0) || (lane == 16);
    const int  my_row   = rowA + (lane >> 4);
    float xp = 0.0f;                 // previous value of my_row

    // This thread's 3 chunks (NCHUNK == 3 * THREADS_SCAN).
    const int ch0 = tid * 3;

    for (int t = 0; t < T_LEN; t++) {
        // ---- hoisted independent load: input projection for this step ----
        float u = 0.f;
        if (is_owner) u = __ldg(g_U + (size_t)t * R_SZ + my_row);

        // ---- acquire state for step t: R5 serial polls ----
        if (t == 0) {
            for (int i = tid; i < R_SZ; i += THREADS_SCAN) s_sm[i] = 0.0f;
        } else {
            const float4* buf = g_chunks[t & 1];
#pragma unroll
            for (int i = 0; i < 3; i++) {
                const int ch  = ch0 + i;
                const int sub = ch % CHUNKS_PER_CTA;              // 0..5
                const int row = (ch / CHUNKS_PER_CTA) * ROWS_PER_CTA + 3 * sub;
                float4 v;
                do {
                    v = ld_chunk_volatile(buf + ch);
                } while (__float_as_int(v.w) != t);
                s_sm[row] = v.x;
                if (sub < 5) { s_sm[row + 1] = v.y; s_sm[row + 2] = v.z; }
            }
        }
        __syncthreads();

        // ---- register-resident matvec with packed f32x2 FMAs ----
        unsigned long long a0 = 0ull, a1 = 0ull;
#pragma unroll
        for (int k = 0; k < 16; k++) {
            const float4 sv = s_sm4[lane + 32 * k];
            const unsigned long long sx = *reinterpret_cast<const unsigned long long*>(&sv.x);
            const unsigned long long sy = *reinterpret_cast<const unsigned long long*>(&sv.z);
            const unsigned long long wax = *reinterpret_cast<const unsigned long long*>(&wA[k].x);
            const unsigned long long way = *reinterpret_cast<const unsigned long long*>(&wA[k].z);
            const unsigned long long wbx = *reinterpret_cast<const unsigned long long*>(&wB[k].x);
            const unsigned long long wby = *reinterpret_cast<const unsigned long long*>(&wB[k].z);
            fma2(a0, wax, sx); fma2(a0, way, sy);
            fma2(a1, wbx, sx); fma2(a1, wby, sy);
        }
        float f0 = unpack_sum(a0);
        float f1 = unpack_sum(a1);

        // ---- split-half reduction: lane 0 -> row A, lane 16 -> row B ----
        f0 += __shfl_xor_sync(0xffffffffu, f0, 16);
        f1 += __shfl_xor_sync(0xffffffffu, f1, 16);
        float v = (lane < 16) ? f0 : f1;
#pragma unroll
        for (int off = 8; off > 0; off >>= 1)
            v += __shfl_xor_sync(0xffffffffu, v, off);

        if (is_owner) {
            const float x = 0.1f * xp + 0.9f * erff(v + u) * INV_SQRT_R;
            xp = x;
            r_sm[2 * warp + (lane >> 4)] = x;
        }
        __syncthreads();

        // ---- publish: tagged chunks (warp 7 lanes 0-5, one STG.128 each,
        //      atomic data+tag => no fence), plain output store (warp 6). ----
        if (warp == 7 && lane < CHUNKS_PER_CTA) {
            float4 c;
            const int r3 = 3 * lane;
            c.x = r_sm[r3];
            c.y = (lane < 5) ? r_sm[r3 + 1] : 0.0f;
            c.z = (lane < 5) ? r_sm[r3 + 2] : 0.0f;
            c.w = __int_as_float(t + 1);
            st_chunk_volatile(&g_chunks[(t + 1) & 1][bid * CHUNKS_PER_CTA + lane], c);
        }
        if (warp == 6 && lane < 4) {
            float4* dst = (float4*)(out + (size_t)t * R_SZ + bid * ROWS_PER_CTA);
            dst[lane] = ((const float4*)r_sm)[lane];
        }
    }
}

// ---------------------------------------------------------------------------
extern "C" void kernel_launch(void* const* d_in, const int* in_sizes, int n_in,
                              void* d_out, int out_size)
{
    const float* input = (const float*)d_in[0];  // [4096][128]
    const float* Win   = (const float*)d_in[1];  // [2048][128]
    const float* Wres  = (const float*)d_in[2];  // [2048][2048]
    const float* bias  = (const float*)d_in[3];  // [2048]
    float* out = (float*)d_out;                  // [4096][2048]

    init_kernel<<<2 * NCHUNK / 256, 256>>>();

    dim3 pg(R_SZ / 64, T_LEN / 64);              // (32, 64)
    proj_kernel<<<pg, 256>>>(input, Win, bias);

    scan_kernel<<<NCTA, THREADS_SCAN>>>(Wres, out);
}